// round 1
// baseline (speedup 1.0000x reference)
#include <cuda_runtime.h>
#include <math.h>

#define D_MODEL 1024
#define NHEAD   16
#define HD      64
#define B_SZ    2
#define SEQ     2048
#define M_TOT   (B_SZ * SEQ)        // 4096 rows for all GEMMs
#define SCALE_F 0.125f              // 64^-0.5

// ---------------------------------------------------------------------------
// Scratch (device globals — no allocations allowed)
// ---------------------------------------------------------------------------
__device__ float g_Q[(size_t)M_TOT * D_MODEL];
__device__ float g_K[(size_t)M_TOT * D_MODEL];
__device__ float g_V[(size_t)M_TOT * D_MODEL];
__device__ float g_O[(size_t)M_TOT * D_MODEL];

// ---------------------------------------------------------------------------
// SGEMM: C[M,N] = A[M,K] @ B[K,N] (+ bias[N])
// BM=BN=128, BK=16, 256 threads, 8x8 register micro-tile per thread.
// ---------------------------------------------------------------------------
#define BM 128
#define BN 128
#define BK 16

__global__ __launch_bounds__(256) void sgemm_kernel(
    const float* __restrict__ A, const float* __restrict__ B,
    const float* __restrict__ bias, float* __restrict__ C,
    int M, int N, int K)
{
    __shared__ float As[BK][BM];   // transposed: As[k][m]
    __shared__ float Bs[BK][BN];

    const int tid = threadIdx.x;           // 0..255
    const int tx  = tid & 15;              // 0..15 -> 8 cols each
    const int ty  = tid >> 4;              // 0..15 -> 8 rows each
    const int bm  = blockIdx.y;
    const int bn  = blockIdx.x;

    const float* Ab = A + (size_t)bm * BM * K;
    const float* Bb = B + (size_t)bn * BN;

    float acc[8][8];
    #pragma unroll
    for (int i = 0; i < 8; i++)
        #pragma unroll
        for (int j = 0; j < 8; j++)
            acc[i][j] = 0.f;

    for (int k0 = 0; k0 < K; k0 += BK) {
        // Load A tile 128x16 (512 float4, 2 per thread), store transposed
        #pragma unroll
        for (int i = 0; i < 2; i++) {
            int f   = tid + i * 256;
            int row = f >> 2;              // 4 float4 per A row
            int c4  = f & 3;
            float4 v = *(const float4*)(Ab + (size_t)row * K + k0 + c4 * 4);
            As[c4 * 4 + 0][row] = v.x;
            As[c4 * 4 + 1][row] = v.y;
            As[c4 * 4 + 2][row] = v.z;
            As[c4 * 4 + 3][row] = v.w;
        }
        // Load B tile 16x128 (512 float4, 2 per thread)
        #pragma unroll
        for (int i = 0; i < 2; i++) {
            int f   = tid + i * 256;
            int row = f >> 5;              // 32 float4 per B row
            int c4  = f & 31;
            *(float4*)(&Bs[row][c4 * 4]) =
                *(const float4*)(Bb + (size_t)(k0 + row) * N + c4 * 4);
        }
        __syncthreads();

        #pragma unroll
        for (int k = 0; k < BK; k++) {
            float a[8], b[8];
            *(float4*)(a)     = *(const float4*)(&As[k][ty * 8]);
            *(float4*)(a + 4) = *(const float4*)(&As[k][ty * 8 + 4]);
            *(float4*)(b)     = *(const float4*)(&Bs[k][tx * 8]);
            *(float4*)(b + 4) = *(const float4*)(&Bs[k][tx * 8 + 4]);
            #pragma unroll
            for (int i = 0; i < 8; i++)
                #pragma unroll
                for (int j = 0; j < 8; j++)
                    acc[i][j] = fmaf(a[i], b[j], acc[i][j]);
        }
        __syncthreads();
    }

    const int crow = bm * BM + ty * 8;
    const int ccol = bn * BN + tx * 8;
    float bv[8];
    #pragma unroll
    for (int j = 0; j < 8; j++)
        bv[j] = bias ? bias[ccol + j] : 0.f;

    #pragma unroll
    for (int i = 0; i < 8; i++) {
        float4 v0, v1;
        v0.x = acc[i][0] + bv[0]; v0.y = acc[i][1] + bv[1];
        v0.z = acc[i][2] + bv[2]; v0.w = acc[i][3] + bv[3];
        v1.x = acc[i][4] + bv[4]; v1.y = acc[i][5] + bv[5];
        v1.z = acc[i][6] + bv[6]; v1.w = acc[i][7] + bv[7];
        float* crow_p = C + (size_t)(crow + i) * N + ccol;
        *(float4*)(crow_p)     = v0;
        *(float4*)(crow_p + 4) = v1;
    }
}

// ---------------------------------------------------------------------------
// Flash attention (fp32, online softmax).
// grid: (SEQ/128, B*NHEAD), block: 128 threads (1 thread = 1 query row).
// KV tiles of 64 rows in static smem (2 * 64*64*4 = 32 KB).
// ---------------------------------------------------------------------------
#define AT_BM 128
#define AT_BN 64

__global__ __launch_bounds__(128) void attn_kernel(
    const float* __restrict__ Qp, const float* __restrict__ Kp,
    const float* __restrict__ Vp, float* __restrict__ Op)
{
    __shared__ float Ks[AT_BN * HD];
    __shared__ float Vs[AT_BN * HD];

    const int t  = threadIdx.x;            // 0..127, query row within tile
    const int bh = blockIdx.y;
    const int b  = bh >> 4;
    const int h  = bh & 15;
    const int m0 = blockIdx.x * AT_BM;

    const size_t rowQ = (size_t)(b * SEQ + m0 + t) * D_MODEL + h * HD;

    float q[HD], o[HD];
    #pragma unroll
    for (int d4 = 0; d4 < HD / 4; d4++) {
        float4 v = *(const float4*)(Qp + rowQ + d4 * 4);
        q[4 * d4 + 0] = v.x; q[4 * d4 + 1] = v.y;
        q[4 * d4 + 2] = v.z; q[4 * d4 + 3] = v.w;
    }
    #pragma unroll
    for (int d = 0; d < HD; d++) o[d] = 0.f;

    float mrun = -INFINITY, l = 0.f;

    for (int n0 = 0; n0 < SEQ; n0 += AT_BN) {
        const size_t kvoff = (size_t)(b * SEQ + n0) * D_MODEL + h * HD;
        const float* kb = Kp + kvoff;
        const float* vb = Vp + kvoff;
        // cooperative load: 64 rows * 16 float4 = 1024 float4, 8 per thread
        #pragma unroll
        for (int i = 0; i < 8; i++) {
            int f   = t + i * 128;
            int row = f >> 4;
            int c4  = f & 15;
            *(float4*)(Ks + row * HD + c4 * 4) =
                *(const float4*)(kb + (size_t)row * D_MODEL + c4 * 4);
            *(float4*)(Vs + row * HD + c4 * 4) =
                *(const float4*)(vb + (size_t)row * D_MODEL + c4 * 4);
        }
        __syncthreads();

        #pragma unroll 1
        for (int jc = 0; jc < AT_BN; jc += 16) {
            float s[16];
            float cmax = -INFINITY;
            #pragma unroll
            for (int jj = 0; jj < 16; jj++) {
                const float* kr = Ks + (jc + jj) * HD;
                float a0 = 0.f, a1 = 0.f, a2 = 0.f, a3 = 0.f;
                #pragma unroll
                for (int d = 0; d < HD; d += 4) {
                    a0 = fmaf(q[d + 0], kr[d + 0], a0);
                    a1 = fmaf(q[d + 1], kr[d + 1], a1);
                    a2 = fmaf(q[d + 2], kr[d + 2], a2);
                    a3 = fmaf(q[d + 3], kr[d + 3], a3);
                }
                float sv = ((a0 + a1) + (a2 + a3)) * SCALE_F;
                s[jj] = sv;
                cmax = fmaxf(cmax, sv);
            }
            float mnew  = fmaxf(mrun, cmax);
            float alpha = __expf(mrun - mnew);   // exp(-inf)=0 on first chunk
            l *= alpha;
            #pragma unroll
            for (int d = 0; d < HD; d++) o[d] *= alpha;
            #pragma unroll
            for (int jj = 0; jj < 16; jj++) {
                float p = __expf(s[jj] - mnew);
                l += p;
                const float* vr = Vs + (jc + jj) * HD;
                #pragma unroll
                for (int d = 0; d < HD; d++)
                    o[d] = fmaf(p, vr[d], o[d]);
            }
            mrun = mnew;
        }
        __syncthreads();
    }

    const float inv = 1.f / l;
    float* orow = Op + rowQ;
    #pragma unroll
    for (int d4 = 0; d4 < HD / 4; d4++) {
        float4 v;
        v.x = o[4 * d4 + 0] * inv; v.y = o[4 * d4 + 1] * inv;
        v.z = o[4 * d4 + 2] * inv; v.w = o[4 * d4 + 3] * inv;
        *(float4*)(orow + d4 * 4) = v;
    }
}

// ---------------------------------------------------------------------------
// Launch: 3 projection GEMMs -> attention -> output GEMM (+bias)
// ---------------------------------------------------------------------------
extern "C" void kernel_launch(void* const* d_in, const int* in_sizes, int n_in,
                              void* d_out, int out_size)
{
    const float* query = (const float*)d_in[0];
    const float* key   = (const float*)d_in[1];
    const float* value = (const float*)d_in[2];
    const float* Wq    = (const float*)d_in[3];
    const float* Wk    = (const float*)d_in[4];
    const float* Wv    = (const float*)d_in[5];
    const float* Wo    = (const float*)d_in[6];
    const float* bo    = (const float*)d_in[7];

    float *Q, *K, *V, *O;
    cudaGetSymbolAddress((void**)&Q, g_Q);
    cudaGetSymbolAddress((void**)&K, g_K);
    cudaGetSymbolAddress((void**)&V, g_V);
    cudaGetSymbolAddress((void**)&O, g_O);

    dim3 gg(D_MODEL / BN, M_TOT / BM);   // (8, 32)

    sgemm_kernel<<<gg, 256>>>(query, Wq, nullptr, Q, M_TOT, D_MODEL, D_MODEL);
    sgemm_kernel<<<gg, 256>>>(key,   Wk, nullptr, K, M_TOT, D_MODEL, D_MODEL);
    sgemm_kernel<<<gg, 256>>>(value, Wv, nullptr, V, M_TOT, D_MODEL, D_MODEL);

    attn_kernel<<<dim3(SEQ / AT_BM, B_SZ * NHEAD), 128>>>(Q, K, V, O);

    sgemm_kernel<<<gg, 256>>>(O, Wo, bo, (float*)d_out, M_TOT, D_MODEL, D_MODEL);
}

// round 2
// speedup vs baseline: 1.0029x; 1.0029x over previous
#include <cuda_runtime.h>
#include <math.h>

#define D_MODEL 1024
#define NHEAD   16
#define HD      64
#define B_SZ    2
#define SEQ     2048
#define M_TOT   (B_SZ * SEQ)        // 4096 rows for all GEMMs
#define SCALE_F 0.125f              // 64^-0.5

// ---------------------------------------------------------------------------
// Scratch (device globals — no allocations allowed)
// ---------------------------------------------------------------------------
__device__ float g_Q[(size_t)M_TOT * D_MODEL];
__device__ float g_K[(size_t)M_TOT * D_MODEL];
__device__ float g_V[(size_t)M_TOT * D_MODEL];
__device__ float g_O[(size_t)M_TOT * D_MODEL];

// ---------------------------------------------------------------------------
// SGEMM: C[M,N] = A[M,K] @ B[K,N] (+ bias[N])
// BM=BN=128, BK=16, 256 threads, 8x8 register micro-tile per thread.
// ---------------------------------------------------------------------------
#define BM 128
#define BN 128
#define BK 16

__global__ __launch_bounds__(256) void sgemm_kernel(
    const float* __restrict__ A, const float* __restrict__ B,
    const float* __restrict__ bias, float* __restrict__ C,
    int M, int N, int K)
{
    __shared__ float As[BK][BM];   // transposed: As[k][m]
    __shared__ float Bs[BK][BN];

    const int tid = threadIdx.x;           // 0..255
    const int tx  = tid & 15;              // 0..15 -> 8 cols each
    const int ty  = tid >> 4;              // 0..15 -> 8 rows each
    const int bm  = blockIdx.y;
    const int bn  = blockIdx.x;

    const float* Ab = A + (size_t)bm * BM * K;
    const float* Bb = B + (size_t)bn * BN;

    float acc[8][8];
    #pragma unroll
    for (int i = 0; i < 8; i++)
        #pragma unroll
        for (int j = 0; j < 8; j++)
            acc[i][j] = 0.f;

    for (int k0 = 0; k0 < K; k0 += BK) {
        // Load A tile 128x16 (512 float4, 2 per thread), store transposed
        #pragma unroll
        for (int i = 0; i < 2; i++) {
            int f   = tid + i * 256;
            int row = f >> 2;              // 4 float4 per A row
            int c4  = f & 3;
            float4 v = *(const float4*)(Ab + (size_t)row * K + k0 + c4 * 4);
            As[c4 * 4 + 0][row] = v.x;
            As[c4 * 4 + 1][row] = v.y;
            As[c4 * 4 + 2][row] = v.z;
            As[c4 * 4 + 3][row] = v.w;
        }
        // Load B tile 16x128 (512 float4, 2 per thread)
        #pragma unroll
        for (int i = 0; i < 2; i++) {
            int f   = tid + i * 256;
            int row = f >> 5;              // 32 float4 per B row
            int c4  = f & 31;
            *(float4*)(&Bs[row][c4 * 4]) =
                *(const float4*)(Bb + (size_t)(k0 + row) * N + c4 * 4);
        }
        __syncthreads();

        #pragma unroll
        for (int k = 0; k < BK; k++) {
            float a[8], b[8];
            *(float4*)(a)     = *(const float4*)(&As[k][ty * 8]);
            *(float4*)(a + 4) = *(const float4*)(&As[k][ty * 8 + 4]);
            *(float4*)(b)     = *(const float4*)(&Bs[k][tx * 8]);
            *(float4*)(b + 4) = *(const float4*)(&Bs[k][tx * 8 + 4]);
            #pragma unroll
            for (int i = 0; i < 8; i++)
                #pragma unroll
                for (int j = 0; j < 8; j++)
                    acc[i][j] = fmaf(a[i], b[j], acc[i][j]);
        }
        __syncthreads();
    }

    const int crow = bm * BM + ty * 8;
    const int ccol = bn * BN + tx * 8;
    float bv[8];
    #pragma unroll
    for (int j = 0; j < 8; j++)
        bv[j] = bias ? bias[ccol + j] : 0.f;

    #pragma unroll
    for (int i = 0; i < 8; i++) {
        float4 v0, v1;
        v0.x = acc[i][0] + bv[0]; v0.y = acc[i][1] + bv[1];
        v0.z = acc[i][2] + bv[2]; v0.w = acc[i][3] + bv[3];
        v1.x = acc[i][4] + bv[4]; v1.y = acc[i][5] + bv[5];
        v1.z = acc[i][6] + bv[6]; v1.w = acc[i][7] + bv[7];
        float* crow_p = C + (size_t)(crow + i) * N + ccol;
        *(float4*)(crow_p)     = v0;
        *(float4*)(crow_p + 4) = v1;
    }
}

// ---------------------------------------------------------------------------
// Flash attention (fp32, online softmax).
// grid: (SEQ/128, B*NHEAD), block: 128 threads (1 thread = 1 query row).
// KV tiles of 64 rows in static smem (2 * 64*64*4 = 32 KB).
// ---------------------------------------------------------------------------
#define AT_BM 128
#define AT_BN 64

__global__ __launch_bounds__(128) void attn_kernel(
    const float* __restrict__ Qp, const float* __restrict__ Kp,
    const float* __restrict__ Vp, float* __restrict__ Op)
{
    __shared__ float Ks[AT_BN * HD];
    __shared__ float Vs[AT_BN * HD];

    const int t  = threadIdx.x;            // 0..127, query row within tile
    const int bh = blockIdx.y;
    const int b  = bh >> 4;
    const int h  = bh & 15;
    const int m0 = blockIdx.x * AT_BM;

    const size_t rowQ = (size_t)(b * SEQ + m0 + t) * D_MODEL + h * HD;

    float q[HD], o[HD];
    #pragma unroll
    for (int d4 = 0; d4 < HD / 4; d4++) {
        float4 v = *(const float4*)(Qp + rowQ + d4 * 4);
        q[4 * d4 + 0] = v.x; q[4 * d4 + 1] = v.y;
        q[4 * d4 + 2] = v.z; q[4 * d4 + 3] = v.w;
    }
    #pragma unroll
    for (int d = 0; d < HD; d++) o[d] = 0.f;

    float mrun = -INFINITY, l = 0.f;

    for (int n0 = 0; n0 < SEQ; n0 += AT_BN) {
        const size_t kvoff = (size_t)(b * SEQ + n0) * D_MODEL + h * HD;
        const float* kb = Kp + kvoff;
        const float* vb = Vp + kvoff;
        // cooperative load: 64 rows * 16 float4 = 1024 float4, 8 per thread
        #pragma unroll
        for (int i = 0; i < 8; i++) {
            int f   = t + i * 128;
            int row = f >> 4;
            int c4  = f & 15;
            *(float4*)(Ks + row * HD + c4 * 4) =
                *(const float4*)(kb + (size_t)row * D_MODEL + c4 * 4);
            *(float4*)(Vs + row * HD + c4 * 4) =
                *(const float4*)(vb + (size_t)row * D_MODEL + c4 * 4);
        }
        __syncthreads();

        #pragma unroll 1
        for (int jc = 0; jc < AT_BN; jc += 16) {
            float s[16];
            float cmax = -INFINITY;
            #pragma unroll
            for (int jj = 0; jj < 16; jj++) {
                const float* kr = Ks + (jc + jj) * HD;
                float a0 = 0.f, a1 = 0.f, a2 = 0.f, a3 = 0.f;
                #pragma unroll
                for (int d = 0; d < HD; d += 4) {
                    a0 = fmaf(q[d + 0], kr[d + 0], a0);
                    a1 = fmaf(q[d + 1], kr[d + 1], a1);
                    a2 = fmaf(q[d + 2], kr[d + 2], a2);
                    a3 = fmaf(q[d + 3], kr[d + 3], a3);
                }
                float sv = ((a0 + a1) + (a2 + a3)) * SCALE_F;
                s[jj] = sv;
                cmax = fmaxf(cmax, sv);
            }
            float mnew  = fmaxf(mrun, cmax);
            float alpha = __expf(mrun - mnew);   // exp(-inf)=0 on first chunk
            l *= alpha;
            #pragma unroll
            for (int d = 0; d < HD; d++) o[d] *= alpha;
            #pragma unroll
            for (int jj = 0; jj < 16; jj++) {
                float p = __expf(s[jj] - mnew);
                l += p;
                const float* vr = Vs + (jc + jj) * HD;
                #pragma unroll
                for (int d = 0; d < HD; d++)
                    o[d] = fmaf(p, vr[d], o[d]);
            }
            mrun = mnew;
        }
        __syncthreads();
    }

    const float inv = 1.f / l;
    float* orow = Op + rowQ;
    #pragma unroll
    for (int d4 = 0; d4 < HD / 4; d4++) {
        float4 v;
        v.x = o[4 * d4 + 0] * inv; v.y = o[4 * d4 + 1] * inv;
        v.z = o[4 * d4 + 2] * inv; v.w = o[4 * d4 + 3] * inv;
        *(float4*)(orow + d4 * 4) = v;
    }
}

// ---------------------------------------------------------------------------
// Launch: 3 projection GEMMs -> attention -> output GEMM (+bias)
// ---------------------------------------------------------------------------
extern "C" void kernel_launch(void* const* d_in, const int* in_sizes, int n_in,
                              void* d_out, int out_size)
{
    const float* query = (const float*)d_in[0];
    const float* key   = (const float*)d_in[1];
    const float* value = (const float*)d_in[2];
    const float* Wq    = (const float*)d_in[3];
    const float* Wk    = (const float*)d_in[4];
    const float* Wv    = (const float*)d_in[5];
    const float* Wo    = (const float*)d_in[6];
    const float* bo    = (const float*)d_in[7];

    float *Q, *K, *V, *O;
    cudaGetSymbolAddress((void**)&Q, g_Q);
    cudaGetSymbolAddress((void**)&K, g_K);
    cudaGetSymbolAddress((void**)&V, g_V);
    cudaGetSymbolAddress((void**)&O, g_O);

    dim3 gg(D_MODEL / BN, M_TOT / BM);   // (8, 32)

    sgemm_kernel<<<gg, 256>>>(query, Wq, nullptr, Q, M_TOT, D_MODEL, D_MODEL);
    sgemm_kernel<<<gg, 256>>>(key,   Wk, nullptr, K, M_TOT, D_MODEL, D_MODEL);
    sgemm_kernel<<<gg, 256>>>(value, Wv, nullptr, V, M_TOT, D_MODEL, D_MODEL);

    attn_kernel<<<dim3(SEQ / AT_BM, B_SZ * NHEAD), 128>>>(Q, K, V, O);

    sgemm_kernel<<<gg, 256>>>(O, Wo, bo, (float*)d_out, M_TOT, D_MODEL, D_MODEL);
}